// round 7
// baseline (speedup 1.0000x reference)
#include <cuda_runtime.h>
#include <cuda_bf16.h>

// CWTConv2D: quantized 3x3 valid conv.
// out[b,i,j,f] = relu( sum_{u,v} round(x[b,i+u,j+v]) * clip(round(kw[f,2-u,2-v]),-1,1)
//                      + round(bias[f]) )
// x (32,512,512) f32, kw (32,3,3) f32, bias (32,) f32 -> out (32,510,510,32) f32 NHWC.
//
// Strategy: warp = 4 output rows x 128 cols, lane = filter channel.
// 2 columns per inner iteration; the 6 window rows each load their 2 new
// columns as one LDS.64. Per 1024 B stored: 6 LDS.64 + 72 FFMA + 8 FMNMX +
// 8 STG -> ~1.75 L1 wavefronts / 128 B (was 4.0), ~12.3 issued instr / 128 B
// (was 15.5). Pushes the kernel from L1/issue-co-limited to HBM-write-bound.

#define BATCH   32
#define HW      512
#define OHW     510
#define NF      32
#define TRW     4                    // output rows per warp
#define TR      (8 * TRW)            // 32 output rows per block
#define TC      128                  // output cols per block
#define SM_ROWS (TR + 2)             // 34 input rows
#define SM_COLS (TC + 2)             // 130 input cols
#define SM_STRIDE 132                // padded (even -> float2 alignment holds)

__global__ __launch_bounds__(256)
void cwtconv2d_kernel(const float* __restrict__ x,
                      const float* __restrict__ kw,
                      const float* __restrict__ bias,
                      float* __restrict__ out)
{
    __shared__ float sx[SM_ROWS * SM_STRIDE];

    const int b   = blockIdx.z;
    const int gr0 = blockIdx.y * TR;
    const int gc0 = blockIdx.x * TC;
    const int tid  = threadIdx.x;
    const int lane = tid & 31;       // filter index
    const int wrp  = tid >> 5;

    // per-lane weights: quantize + double flip (raster-order dot with x patch)
    float wf[9];
    #pragma unroll
    for (int k = 0; k < 9; ++k) {
        float v = rintf(__ldg(&kw[lane * 9 + (8 - k)]));
        wf[k] = fminf(fmaxf(v, -1.0f), 1.0f);
    }
    const float bia = rintf(__ldg(&bias[lane]));

    // cooperative fill: pre-rounded input tile (coalesced reads, linear STS)
    const float* xb = x + (size_t)b * HW * HW;
    for (int idx = tid; idx < SM_ROWS * SM_COLS; idx += 256) {
        int r = idx / SM_COLS;
        int c = idx - r * SM_COLS;
        int gr = gr0 + r;
        int gc = gc0 + c;
        float v = 0.0f;
        if (gr < HW && gc < HW) v = rintf(xb[gr * HW + gc]);
        sx[r * SM_STRIDE + c] = v;
    }
    __syncthreads();

    const int r0 = wrp * TRW;        // warp's first output row within tile

    int jmax = OHW - gc0;            // 128 or 126 -> always even
    if (jmax > TC) jmax = TC;

    // output row validity + store pointers
    bool  ok[TRW];
    float* op[TRW];
    #pragma unroll
    for (int k = 0; k < TRW; ++k) {
        int row = gr0 + r0 + k;
        ok[k] = (row < OHW);
        int rr = ok[k] ? row : 0;    // keep pointer arithmetic in-range
        op[k] = out + (((size_t)b * OHW + rr) * OHW + gc0) * NF + lane;
    }

    // window registers: 6 rows x (col j, col j+1)
    float A[TRW + 2], B[TRW + 2];
    #pragma unroll
    for (int k = 0; k < TRW + 2; ++k) {
        A[k] = sx[(r0 + k) * SM_STRIDE + 0];
        B[k] = sx[(r0 + k) * SM_STRIDE + 1];
    }

    #pragma unroll 2
    for (int j = 0; j < jmax; j += 2) {
        // load the 2 new columns for all 6 rows (aligned float2, broadcast)
        float2 N[TRW + 2];
        #pragma unroll
        for (int k = 0; k < TRW + 2; ++k)
            N[k] = *(const float2*)&sx[(r0 + k) * SM_STRIDE + j + 2];

        #pragma unroll
        for (int k = 0; k < TRW; ++k) {
            // pixel (row k, col j): cols A,B,N.x over rows k..k+2
            float a0 = bia;
            a0 = fmaf(A[k    ], wf[0], a0);
            a0 = fmaf(B[k    ], wf[1], a0);
            a0 = fmaf(N[k    ].x, wf[2], a0);
            a0 = fmaf(A[k + 1], wf[3], a0);
            a0 = fmaf(B[k + 1], wf[4], a0);
            a0 = fmaf(N[k + 1].x, wf[5], a0);
            a0 = fmaf(A[k + 2], wf[6], a0);
            a0 = fmaf(B[k + 2], wf[7], a0);
            a0 = fmaf(N[k + 2].x, wf[8], a0);

            // pixel (row k, col j+1): cols B,N.x,N.y
            float a1 = bia;
            a1 = fmaf(B[k    ], wf[0], a1);
            a1 = fmaf(N[k    ].x, wf[1], a1);
            a1 = fmaf(N[k    ].y, wf[2], a1);
            a1 = fmaf(B[k + 1], wf[3], a1);
            a1 = fmaf(N[k + 1].x, wf[4], a1);
            a1 = fmaf(N[k + 1].y, wf[5], a1);
            a1 = fmaf(B[k + 2], wf[6], a1);
            a1 = fmaf(N[k + 2].x, wf[7], a1);
            a1 = fmaf(N[k + 2].y, wf[8], a1);

            if (ok[k]) {
                op[k][0]  = fmaxf(a0, 0.0f);   // col j   (128 B coalesced)
                op[k][NF] = fmaxf(a1, 0.0f);   // col j+1 (128 B coalesced)
            }
            op[k] += 2 * NF;
        }

        // slide window by 2: full replacement -> register rotation, no MOVs
        #pragma unroll
        for (int k = 0; k < TRW + 2; ++k) {
            A[k] = N[k].x;
            B[k] = N[k].y;
        }
    }
}

extern "C" void kernel_launch(void* const* d_in, const int* in_sizes, int n_in,
                              void* d_out, int out_size)
{
    const float* x    = (const float*)d_in[0];
    const float* kw   = (const float*)d_in[1];
    const float* bias = (const float*)d_in[2];
    float* out = (float*)d_out;

    dim3 grid((OHW + TC - 1) / TC,   // 4
              (OHW + TR - 1) / TR,   // 16
              BATCH);                // 32 -> 2048 blocks
    cwtconv2d_kernel<<<grid, 256>>>(x, kw, bias, out);
}

// round 9
// speedup vs baseline: 1.0632x; 1.0632x over previous
#include <cuda_runtime.h>
#include <cuda_bf16.h>

// CWTConv2D: quantized 3x3 valid conv.
// out[b,i,j,f] = relu( sum_{u,v} round(x[b,i+u,j+v]) * clip(round(kw[f,2-u,2-v]),-1,1)
//                      + round(bias[f]) )
// x (32,512,512) f32, kw (32,3,3) f32, bias (32,) f32 -> out (32,510,510,32) f32 NHWC.
//
// Design (R7): warp = 1 output row x 128 cols, lane = filter channel.
//  - div-free vectorized smem fill (float4 LDG/STS, shift-based indexing)
//  - 4 output cols per inner iteration; sliding window holds cols j..j+3,
//    loads cols j+4..j+7 as one aligned LDS.128 per row (3 rows)
//  - per 4 pixels (512 B stored): 3 LDS.128 + 36 FFMA + 4 FMNMX + 4 STG
//  - __launch_bounds__(256,6): <=42 regs -> 48 warps/SM (75% occ)

#define BATCH   32
#define HW      512
#define OHW     510
#define NF      32
#define TR      8                    // output rows per block (1 per warp)
#define TC      128                  // output cols per block
#define SM_ROWS (TR + 2)             // 10 input rows
#define SM_STRIDE 132                // 130 needed cols + pad; mult of 4 -> f4 aligned

__global__ __launch_bounds__(256, 6)
void cwtconv2d_kernel(const float* __restrict__ x,
                      const float* __restrict__ kw,
                      const float* __restrict__ bias,
                      float* __restrict__ out)
{
    __shared__ float sx[SM_ROWS * SM_STRIDE];

    const int b   = blockIdx.z;
    const int gr0 = blockIdx.y * TR;
    const int gc0 = blockIdx.x * TC;
    const int tid  = threadIdx.x;
    const int lane = tid & 31;       // filter index
    const int wrp  = tid >> 5;       // output row within tile

    // per-lane weights: quantize + double flip (raster-order dot with x patch)
    float wf0, wf1, wf2, wf3, wf4, wf5, wf6, wf7, wf8;
    {
        const float* kp = kw + lane * 9;
        #define QW(i) fminf(fmaxf(rintf(__ldg(&kp[8 - (i)])), -1.0f), 1.0f)
        wf0 = QW(0); wf1 = QW(1); wf2 = QW(2);
        wf3 = QW(3); wf4 = QW(4); wf5 = QW(5);
        wf6 = QW(6); wf7 = QW(7); wf8 = QW(8);
        #undef QW
    }
    const float bia = rintf(__ldg(&bias[lane]));

    // ---- div-free vectorized fill: 10 rows x 32 float4 tasks (cols 0..127) ----
    // cols gc0..gc0+127 are always in-bounds (gc0 <= 384); only rows need guards.
    const float* xb = x + (size_t)b * HW * HW;
    #pragma unroll
    for (int t = tid; t < SM_ROWS * 32; t += 256) {   // 320 tasks
        int r = t >> 5;
        int k = (t & 31) << 2;
        int gr = gr0 + r;
        float4 v = make_float4(0.f, 0.f, 0.f, 0.f);
        if (gr < HW)
            v = *(const float4*)&xb[gr * HW + gc0 + k];
        v.x = rintf(v.x); v.y = rintf(v.y); v.z = rintf(v.z); v.w = rintf(v.w);
        *(float4*)&sx[r * SM_STRIDE + k] = v;
    }
    // tail: tile cols 128..131 (col 130/131 loaded by last LDS.128 but unused)
    if (tid < SM_ROWS * 4) {         // 40 threads
        int r = tid >> 2;
        int c = 128 + (tid & 3);
        int gr = gr0 + r;
        int gc = gc0 + c;
        float v = 0.0f;
        if (gr < HW && gc < HW) v = rintf(xb[gr * HW + gc]);
        sx[r * SM_STRIDE + c] = v;
    }
    __syncthreads();

    const int i = gr0 + wrp;
    if (i >= OHW) return;

    int jmax = OHW - gc0;            // 128,128,128,126
    if (jmax > TC) jmax = TC;

    const float* s0 = &sx[wrp * SM_STRIDE];

    // held window: cols j..j+3 for the 3 input rows
    float4 H0 = *(const float4*)&s0[0];
    float4 H1 = *(const float4*)&s0[SM_STRIDE];
    float4 H2 = *(const float4*)&s0[2 * SM_STRIDE];

    float* op = out + (((size_t)b * OHW + i) * OHW + gc0) * NF + lane;

    #pragma unroll 2
    for (int j = 0; j < jmax; j += 4) {
        // next 4 cols per row (aligned LDS.128; j+4 <= 128 -> within 132-col tile)
        float4 N0 = *(const float4*)&s0[j + 4];
        float4 N1 = *(const float4*)&s0[SM_STRIDE + j + 4];
        float4 N2 = *(const float4*)&s0[2 * SM_STRIDE + j + 4];

        float a0 = bia, a1 = bia, a2 = bia, a3 = bia;

        // row 0 taps (wf0..wf2)
        a0 = fmaf(H0.x, wf0, a0); a0 = fmaf(H0.y, wf1, a0); a0 = fmaf(H0.z, wf2, a0);
        a1 = fmaf(H0.y, wf0, a1); a1 = fmaf(H0.z, wf1, a1); a1 = fmaf(H0.w, wf2, a1);
        a2 = fmaf(H0.z, wf0, a2); a2 = fmaf(H0.w, wf1, a2); a2 = fmaf(N0.x, wf2, a2);
        a3 = fmaf(H0.w, wf0, a3); a3 = fmaf(N0.x, wf1, a3); a3 = fmaf(N0.y, wf2, a3);
        // row 1 taps (wf3..wf5)
        a0 = fmaf(H1.x, wf3, a0); a0 = fmaf(H1.y, wf4, a0); a0 = fmaf(H1.z, wf5, a0);
        a1 = fmaf(H1.y, wf3, a1); a1 = fmaf(H1.z, wf4, a1); a1 = fmaf(H1.w, wf5, a1);
        a2 = fmaf(H1.z, wf3, a2); a2 = fmaf(H1.w, wf4, a2); a2 = fmaf(N1.x, wf5, a2);
        a3 = fmaf(H1.w, wf3, a3); a3 = fmaf(N1.x, wf4, a3); a3 = fmaf(N1.y, wf5, a3);
        // row 2 taps (wf6..wf8)
        a0 = fmaf(H2.x, wf6, a0); a0 = fmaf(H2.y, wf7, a0); a0 = fmaf(H2.z, wf8, a0);
        a1 = fmaf(H2.y, wf6, a1); a1 = fmaf(H2.z, wf7, a1); a1 = fmaf(H2.w, wf8, a1);
        a2 = fmaf(H2.z, wf6, a2); a2 = fmaf(H2.w, wf7, a2); a2 = fmaf(N2.x, wf8, a2);
        a3 = fmaf(H2.w, wf6, a3); a3 = fmaf(N2.x, wf7, a3); a3 = fmaf(N2.y, wf8, a3);

        if (j + 4 <= jmax) {
            // fast path (all blocks except the last column-block's last iter)
            op[0 * NF] = fmaxf(a0, 0.0f);
            op[1 * NF] = fmaxf(a1, 0.0f);
            op[2 * NF] = fmaxf(a2, 0.0f);
            op[3 * NF] = fmaxf(a3, 0.0f);
        } else {
            if (j + 0 < jmax) op[0 * NF] = fmaxf(a0, 0.0f);
            if (j + 1 < jmax) op[1 * NF] = fmaxf(a1, 0.0f);
            if (j + 2 < jmax) op[2 * NF] = fmaxf(a2, 0.0f);
            if (j + 3 < jmax) op[3 * NF] = fmaxf(a3, 0.0f);
        }
        op += 4 * NF;

        // slide window by 4: full replacement -> register rotation under unroll
        H0 = N0; H1 = N1; H2 = N2;
    }
}

extern "C" void kernel_launch(void* const* d_in, const int* in_sizes, int n_in,
                              void* d_out, int out_size)
{
    const float* x    = (const float*)d_in[0];
    const float* kw   = (const float*)d_in[1];
    const float* bias = (const float*)d_in[2];
    float* out = (float*)d_out;

    dim3 grid((OHW + TC - 1) / TC,   // 4
              (OHW + TR - 1) / TR,   // 64
              BATCH);                // 32 -> 8192 blocks
    cwtconv2d_kernel<<<grid, 256>>>(x, kw, bias, out);
}

// round 10
// speedup vs baseline: 1.0664x; 1.0030x over previous
#include <cuda_runtime.h>
#include <cuda_bf16.h>

// CWTConv2D: quantized 3x3 valid conv.
// out[b,i,j,f] = relu( sum_{u,v} round(x[b,i+u,j+v]) * clip(round(kw[f,2-u,2-v]),-1,1)
//                      + round(bias[f]) )
// x (32,512,512) f32, kw (32,3,3) f32, bias (32,) f32 -> out (32,510,510,32) f32 NHWC.
//
// Design (R7): warp = 1 output row x 128 cols, lane = filter channel.
//  - div-free vectorized smem fill (float4 LDG/STS, shift-based indexing)
//  - 4 output cols per inner iteration; sliding window holds cols j..j+3,
//    loads cols j+4..j+7 as one aligned LDS.128 per row (3 rows)
//  - per 4 pixels (512 B stored): 3 LDS.128 + 36 FFMA + 4 FMNMX + 4 STG
//  - __launch_bounds__(256,6): <=42 regs -> 48 warps/SM (75% occ)

#define BATCH   32
#define HW      512
#define OHW     510
#define NF      32
#define TR      8                    // output rows per block (1 per warp)
#define TC      128                  // output cols per block
#define SM_ROWS (TR + 2)             // 10 input rows
#define SM_STRIDE 132                // 130 needed cols + pad; mult of 4 -> f4 aligned

__global__ __launch_bounds__(256, 6)
void cwtconv2d_kernel(const float* __restrict__ x,
                      const float* __restrict__ kw,
                      const float* __restrict__ bias,
                      float* __restrict__ out)
{
    __shared__ float sx[SM_ROWS * SM_STRIDE];

    const int b   = blockIdx.z;
    const int gr0 = blockIdx.y * TR;
    const int gc0 = blockIdx.x * TC;
    const int tid  = threadIdx.x;
    const int lane = tid & 31;       // filter index
    const int wrp  = tid >> 5;       // output row within tile

    // per-lane weights: quantize + double flip (raster-order dot with x patch)
    float wf0, wf1, wf2, wf3, wf4, wf5, wf6, wf7, wf8;
    {
        const float* kp = kw + lane * 9;
        #define QW(i) fminf(fmaxf(rintf(__ldg(&kp[8 - (i)])), -1.0f), 1.0f)
        wf0 = QW(0); wf1 = QW(1); wf2 = QW(2);
        wf3 = QW(3); wf4 = QW(4); wf5 = QW(5);
        wf6 = QW(6); wf7 = QW(7); wf8 = QW(8);
        #undef QW
    }
    const float bia = rintf(__ldg(&bias[lane]));

    // ---- div-free vectorized fill: 10 rows x 32 float4 tasks (cols 0..127) ----
    // cols gc0..gc0+127 are always in-bounds (gc0 <= 384); only rows need guards.
    const float* xb = x + (size_t)b * HW * HW;
    #pragma unroll
    for (int t = tid; t < SM_ROWS * 32; t += 256) {   // 320 tasks
        int r = t >> 5;
        int k = (t & 31) << 2;
        int gr = gr0 + r;
        float4 v = make_float4(0.f, 0.f, 0.f, 0.f);
        if (gr < HW)
            v = *(const float4*)&xb[gr * HW + gc0 + k];
        v.x = rintf(v.x); v.y = rintf(v.y); v.z = rintf(v.z); v.w = rintf(v.w);
        *(float4*)&sx[r * SM_STRIDE + k] = v;
    }
    // tail: tile cols 128..131 (col 130/131 loaded by last LDS.128 but unused)
    if (tid < SM_ROWS * 4) {         // 40 threads
        int r = tid >> 2;
        int c = 128 + (tid & 3);
        int gr = gr0 + r;
        int gc = gc0 + c;
        float v = 0.0f;
        if (gr < HW && gc < HW) v = rintf(xb[gr * HW + gc]);
        sx[r * SM_STRIDE + c] = v;
    }
    __syncthreads();

    const int i = gr0 + wrp;
    if (i >= OHW) return;

    int jmax = OHW - gc0;            // 128,128,128,126
    if (jmax > TC) jmax = TC;

    const float* s0 = &sx[wrp * SM_STRIDE];

    // held window: cols j..j+3 for the 3 input rows
    float4 H0 = *(const float4*)&s0[0];
    float4 H1 = *(const float4*)&s0[SM_STRIDE];
    float4 H2 = *(const float4*)&s0[2 * SM_STRIDE];

    float* op = out + (((size_t)b * OHW + i) * OHW + gc0) * NF + lane;

    #pragma unroll 2
    for (int j = 0; j < jmax; j += 4) {
        // next 4 cols per row (aligned LDS.128; j+4 <= 128 -> within 132-col tile)
        float4 N0 = *(const float4*)&s0[j + 4];
        float4 N1 = *(const float4*)&s0[SM_STRIDE + j + 4];
        float4 N2 = *(const float4*)&s0[2 * SM_STRIDE + j + 4];

        float a0 = bia, a1 = bia, a2 = bia, a3 = bia;

        // row 0 taps (wf0..wf2)
        a0 = fmaf(H0.x, wf0, a0); a0 = fmaf(H0.y, wf1, a0); a0 = fmaf(H0.z, wf2, a0);
        a1 = fmaf(H0.y, wf0, a1); a1 = fmaf(H0.z, wf1, a1); a1 = fmaf(H0.w, wf2, a1);
        a2 = fmaf(H0.z, wf0, a2); a2 = fmaf(H0.w, wf1, a2); a2 = fmaf(N0.x, wf2, a2);
        a3 = fmaf(H0.w, wf0, a3); a3 = fmaf(N0.x, wf1, a3); a3 = fmaf(N0.y, wf2, a3);
        // row 1 taps (wf3..wf5)
        a0 = fmaf(H1.x, wf3, a0); a0 = fmaf(H1.y, wf4, a0); a0 = fmaf(H1.z, wf5, a0);
        a1 = fmaf(H1.y, wf3, a1); a1 = fmaf(H1.z, wf4, a1); a1 = fmaf(H1.w, wf5, a1);
        a2 = fmaf(H1.z, wf3, a2); a2 = fmaf(H1.w, wf4, a2); a2 = fmaf(N1.x, wf5, a2);
        a3 = fmaf(H1.w, wf3, a3); a3 = fmaf(N1.x, wf4, a3); a3 = fmaf(N1.y, wf5, a3);
        // row 2 taps (wf6..wf8)
        a0 = fmaf(H2.x, wf6, a0); a0 = fmaf(H2.y, wf7, a0); a0 = fmaf(H2.z, wf8, a0);
        a1 = fmaf(H2.y, wf6, a1); a1 = fmaf(H2.z, wf7, a1); a1 = fmaf(H2.w, wf8, a1);
        a2 = fmaf(H2.z, wf6, a2); a2 = fmaf(H2.w, wf7, a2); a2 = fmaf(N2.x, wf8, a2);
        a3 = fmaf(H2.w, wf6, a3); a3 = fmaf(N2.x, wf7, a3); a3 = fmaf(N2.y, wf8, a3);

        if (j + 4 <= jmax) {
            // fast path (all blocks except the last column-block's last iter)
            op[0 * NF] = fmaxf(a0, 0.0f);
            op[1 * NF] = fmaxf(a1, 0.0f);
            op[2 * NF] = fmaxf(a2, 0.0f);
            op[3 * NF] = fmaxf(a3, 0.0f);
        } else {
            if (j + 0 < jmax) op[0 * NF] = fmaxf(a0, 0.0f);
            if (j + 1 < jmax) op[1 * NF] = fmaxf(a1, 0.0f);
            if (j + 2 < jmax) op[2 * NF] = fmaxf(a2, 0.0f);
            if (j + 3 < jmax) op[3 * NF] = fmaxf(a3, 0.0f);
        }
        op += 4 * NF;

        // slide window by 4: full replacement -> register rotation under unroll
        H0 = N0; H1 = N1; H2 = N2;
    }
}

extern "C" void kernel_launch(void* const* d_in, const int* in_sizes, int n_in,
                              void* d_out, int out_size)
{
    const float* x    = (const float*)d_in[0];
    const float* kw   = (const float*)d_in[1];
    const float* bias = (const float*)d_in[2];
    float* out = (float*)d_out;

    dim3 grid((OHW + TC - 1) / TC,   // 4
              (OHW + TR - 1) / TR,   // 64
              BATCH);                // 32 -> 8192 blocks
    cwtconv2d_kernel<<<grid, 256>>>(x, kw, bias, out);
}